// round 15
// baseline (speedup 1.0000x reference)
#include <cuda_runtime.h>
#include <cuda_fp16.h>
#include <cstdint>

#define NU 100000
#define NI 100000
#define D  128
#define EMAX 810000
#define NROWS 100000
#define SCAN_NB ((NROWS + 1023) / 1024)

typedef __half h16;
typedef unsigned int u32;

// ---------------- scratch ----------------------------------------------------
__device__ h16 g_f16_u[(size_t)NU * D];   // fp16 feat_user
__device__ h16 g_f16_i[(size_t)NI * D];   // fp16 feat_item
__device__ h16 g_a_f [(size_t)NU * D];
__device__ h16 g_a_rb[(size_t)NU * D];
__device__ h16 g_a_r [(size_t)NI * D];
__device__ h16 g_w16[3 * D * D];
__device__ int g_hist_f [NU];
__device__ int g_hist_rb[NU];
__device__ int g_hist_r [NI];
__device__ int g_ptr_f [NU + 1];
__device__ int g_ptr_rb[NU + 1];
__device__ int g_ptr_r [NI + 1];
__device__ int g_cur_f [NU];
__device__ int g_cur_rb[NU];
__device__ int g_cur_r [NI];
__device__ int g_srcl_f [EMAX];
__device__ int g_srcl_rb[EMAX];
__device__ int g_srcl_r [EMAX];
__device__ int g_bsum[3 * SCAN_NB];
__device__ int g_boff[3 * SCAN_NB];

static __device__ __forceinline__ const int* hist_of(int et) {
    return (et == 0) ? g_hist_f : (et == 1) ? g_hist_rb : g_hist_r;
}
static __device__ __forceinline__ int* ptr_of(int et) {
    return (et == 0) ? g_ptr_f : (et == 1) ? g_ptr_rb : g_ptr_r;
}
static __device__ __forceinline__ int* cur_of(int et) {
    return (et == 0) ? g_cur_f : (et == 1) ? g_cur_rb : g_cur_r;
}

// ---------------- zero histograms --------------------------------------------
__global__ void zero_hist_kernel() {
    int i = blockIdx.x * blockDim.x + threadIdx.x;
    if (i < NU) { g_hist_f[i] = 0; g_hist_rb[i] = 0; g_hist_r[i] = 0; }
}

// ---------------- feat fp32 -> fp16 conversion --------------------------------
__global__ __launch_bounds__(256) void fconv_kernel(
    const float4* __restrict__ fu, const float4* __restrict__ fi)
{
    // each thread converts 4 floats -> 4 halves (uint2)
    size_t i = (size_t)blockIdx.x * blockDim.x + threadIdx.x;
    const size_t n4 = (size_t)NU * D / 4;
    if (i >= n4) return;
    float4 a = fu[i];
    float4 b = fi[i];
    u32 a0 = (u32)__half_as_ushort(__float2half_rn(a.x))
           | ((u32)__half_as_ushort(__float2half_rn(a.y)) << 16);
    u32 a1 = (u32)__half_as_ushort(__float2half_rn(a.z))
           | ((u32)__half_as_ushort(__float2half_rn(a.w)) << 16);
    u32 b0 = (u32)__half_as_ushort(__float2half_rn(b.x))
           | ((u32)__half_as_ushort(__float2half_rn(b.y)) << 16);
    u32 b1 = (u32)__half_as_ushort(__float2half_rn(b.z))
           | ((u32)__half_as_ushort(__float2half_rn(b.w)) << 16);
    reinterpret_cast<uint2*>(g_f16_u)[i] = make_uint2(a0, a1);
    reinterpret_cast<uint2*>(g_f16_i)[i] = make_uint2(b0, b1);
}

// ---------------- fused histogram ---------------------------------------------
__global__ __launch_bounds__(256) void hist3_kernel(
    const int* __restrict__ d0, const int* __restrict__ d1,
    const int* __restrict__ d2, int E0, int E1, int E2)
{
    int et = blockIdx.y;
    const int* dst = (et == 0) ? d0 : (et == 1) ? d1 : d2;
    int* hist = (et == 0) ? g_hist_f : (et == 1) ? g_hist_rb : g_hist_r;
    int E = (et == 0) ? E0 : (et == 1) ? E1 : E2;
    int i = blockIdx.x * blockDim.x + threadIdx.x;
    if (i < E) atomicAdd(&hist[dst[i]], 1);
}

// ---------------- 3-phase full-chip exclusive scan ----------------------------
__global__ __launch_bounds__(256) void scan_p1()
{
    int et = blockIdx.y;
    const int* hist = hist_of(et);
    int i0 = blockIdx.x * 1024 + threadIdx.x * 4;
    int s = 0;
#pragma unroll
    for (int j = 0; j < 4; j++)
        if (i0 + j < NROWS) s += hist[i0 + j];
    int lane = threadIdx.x & 31, wid = threadIdx.x >> 5;
#pragma unroll
    for (int off = 16; off > 0; off >>= 1)
        s += __shfl_down_sync(0xffffffffu, s, off);
    __shared__ int ws[8];
    if (lane == 0) ws[wid] = s;
    __syncthreads();
    if (threadIdx.x == 0) {
        int tot = 0;
#pragma unroll
        for (int w = 0; w < 8; w++) tot += ws[w];
        g_bsum[et * SCAN_NB + blockIdx.x] = tot;
    }
}

__global__ void scan_p2()
{
    int et = threadIdx.x;
    if (et >= 3) return;
    int run = 0;
    for (int b = 0; b < SCAN_NB; b++) {
        g_boff[et * SCAN_NB + b] = run;
        run += g_bsum[et * SCAN_NB + b];
    }
    ptr_of(et)[NROWS] = run;
}

__global__ __launch_bounds__(256) void scan_p3()
{
    int et = blockIdx.y;
    const int* hist = hist_of(et);
    int* ptr = ptr_of(et);
    int* cur = cur_of(et);
    int i0 = blockIdx.x * 1024 + threadIdx.x * 4;

    int h[4];
    int thsum = 0;
#pragma unroll
    for (int j = 0; j < 4; j++) {
        h[j] = (i0 + j < NROWS) ? hist[i0 + j] : 0;
        thsum += h[j];
    }
    int lane = threadIdx.x & 31, wid = threadIdx.x >> 5;
    int incl = thsum;
#pragma unroll
    for (int off = 1; off < 32; off <<= 1) {
        int t = __shfl_up_sync(0xffffffffu, incl, off);
        if (lane >= off) incl += t;
    }
    __shared__ int ws[8];
    if (lane == 31) ws[wid] = incl;
    __syncthreads();
    int wofs = 0;
#pragma unroll
    for (int w = 0; w < 8; w++)
        if (w < wid) wofs += ws[w];
    int excl = incl - thsum + wofs + g_boff[et * SCAN_NB + blockIdx.x];
#pragma unroll
    for (int j = 0; j < 4; j++) {
        if (i0 + j < NROWS) {
            ptr[i0 + j] = excl;
            cur[i0 + j] = excl;
        }
        excl += h[j];
    }
}

// ---------------- fused permute -----------------------------------------------
__global__ __launch_bounds__(256) void permute3_kernel(
    const int* __restrict__ s0, const int* __restrict__ d0,
    const int* __restrict__ s1, const int* __restrict__ d1,
    const int* __restrict__ s2, const int* __restrict__ d2,
    int E0, int E1, int E2)
{
    int et = blockIdx.y;
    const int* src = (et == 0) ? s0 : (et == 1) ? s1 : s2;
    const int* dst = (et == 0) ? d0 : (et == 1) ? d1 : d2;
    int* cur = cur_of(et);
    int* srclist = (et == 0) ? g_srcl_f : (et == 1) ? g_srcl_rb : g_srcl_r;
    int E = (et == 0) ? E0 : (et == 1) ? E1 : E2;
    int i = blockIdx.x * blockDim.x + threadIdx.x;
    if (i < E) {
        int d = dst[i];
        int p = atomicAdd(&cur[d], 1);
        srclist[p] = src[i];
    }
}

// ---------------- W fp16 prep --------------------------------------------------
__global__ void wprep_kernel(const float* __restrict__ Wf,
                             const float* __restrict__ Wrb,
                             const float* __restrict__ Wr)
{
    int et = blockIdx.x;
    const float* W = (et == 0) ? Wf : (et == 1) ? Wrb : Wr;
    h16* w = g_w16 + et * D * D;
    for (int i = threadIdx.x; i < D * D; i += blockDim.x)
        w[i] = __float2half_rn(W[i]);
}

// ---------------- fused gather (fp16 feat rows, fp32 accumulate) --------------
__global__ __launch_bounds__(256) void gather3_kernel()
{
    int et = blockIdx.y;
    const uint2* feat = reinterpret_cast<const uint2*>((et == 1) ? g_f16_i : g_f16_u);
    const int* ptr = (et == 0) ? g_ptr_f : (et == 1) ? g_ptr_rb : g_ptr_r;
    const int* srclist = (et == 0) ? g_srcl_f : (et == 1) ? g_srcl_rb : g_srcl_r;
    h16* a = (et == 0) ? g_a_f : (et == 1) ? g_a_rb : g_a_r;

    int node = (blockIdx.x * 256 + threadIdx.x) >> 5;
    int lane = threadIdx.x & 31;
    if (node >= NROWS) return;
    int beg = __ldg(&ptr[node]);
    int end = __ldg(&ptr[node + 1]);
    int deg = end - beg;

    float4 s = make_float4(0.f, 0.f, 0.f, 0.f);
    int e = beg;
    for (; e + 8 <= end; e += 8) {
        int si[8];
#pragma unroll
        for (int j = 0; j < 8; j++) si[j] = __ldg(&srclist[e + j]);
        uint2 v[8];
#pragma unroll
        for (int j = 0; j < 8; j++) v[j] = feat[(size_t)si[j] * 32 + lane];
#pragma unroll
        for (int j = 0; j < 8; j++) {
            float2 f0 = __half22float2(*reinterpret_cast<__half2*>(&v[j].x));
            float2 f1 = __half22float2(*reinterpret_cast<__half2*>(&v[j].y));
            s.x += f0.x; s.y += f0.y; s.z += f1.x; s.w += f1.y;
        }
    }
    for (; e + 4 <= end; e += 4) {
        int si[4];
#pragma unroll
        for (int j = 0; j < 4; j++) si[j] = __ldg(&srclist[e + j]);
        uint2 v[4];
#pragma unroll
        for (int j = 0; j < 4; j++) v[j] = feat[(size_t)si[j] * 32 + lane];
#pragma unroll
        for (int j = 0; j < 4; j++) {
            float2 f0 = __half22float2(*reinterpret_cast<__half2*>(&v[j].x));
            float2 f1 = __half22float2(*reinterpret_cast<__half2*>(&v[j].y));
            s.x += f0.x; s.y += f0.y; s.z += f1.x; s.w += f1.y;
        }
    }
    for (; e < end; e++) {
        uint2 v = feat[(size_t)__ldg(&srclist[e]) * 32 + lane];
        float2 f0 = __half22float2(*reinterpret_cast<__half2*>(&v.x));
        float2 f1 = __half22float2(*reinterpret_cast<__half2*>(&v.y));
        s.x += f0.x; s.y += f0.y; s.z += f1.x; s.w += f1.y;
    }
    float inv = __fdividef(1.0f, (float)(deg > 0 ? deg : 1));

    u32 p0 = (u32)__half_as_ushort(__float2half_rn(s.x * inv))
           | ((u32)__half_as_ushort(__float2half_rn(s.y * inv)) << 16);
    u32 p1 = (u32)__half_as_ushort(__float2half_rn(s.z * inv))
           | ((u32)__half_as_ushort(__float2half_rn(s.w * inv)) << 16);
    *reinterpret_cast<uint2*>(a + (size_t)node * D + lane * 4) = make_uint2(p0, p1);
}

// ---------------- fp16 mma.sync GEMM (single product) -------------------------
#define ASTR 72

static __device__ __forceinline__ void mma_f16(float* c, const u32* a, u32 b0, u32 b1) {
    asm volatile(
        "mma.sync.aligned.m16n8k16.row.col.f32.f16.f16.f32 "
        "{%0,%1,%2,%3}, {%4,%5,%6,%7}, {%8,%9}, {%0,%1,%2,%3};"
        : "+f"(c[0]), "+f"(c[1]), "+f"(c[2]), "+f"(c[3])
        : "r"(a[0]), "r"(a[1]), "r"(a[2]), "r"(a[3]), "r"(b0), "r"(b1));
}
static __device__ __forceinline__ void ldsm_x4(u32& d0, u32& d1, u32& d2, u32& d3, u32 addr) {
    asm volatile("ldmatrix.sync.aligned.m8n8.x4.shared.b16 {%0,%1,%2,%3}, [%4];"
                 : "=r"(d0), "=r"(d1), "=r"(d2), "=r"(d3) : "r"(addr));
}

__global__ __launch_bounds__(256, 2) void gemm_mma(
    float* __restrict__ out_user, float* __restrict__ out_item,
    const float* __restrict__ b_f, const float* __restrict__ b_rb,
    const float* __restrict__ b_r)
{
    __shared__ __align__(16) h16 As[128 * ASTR];
    __shared__ __align__(16) h16 Bs[128 * ASTR];

    const int tid = threadIdx.x;
    const int wid = tid >> 5, lane = tid & 31;
    const int g = lane >> 2, t = lane & 3;
    const int q = lane >> 3, rr = lane & 7;
    const int row0 = blockIdx.x * 128;
    const bool user = (blockIdx.y == 0);
    const int nsegs = user ? 2 : 1;

    const int wm0 = (wid >> 1) * 32;
    const int wn0 = (wid & 1) * 64;

    float C[2][8][4];
#pragma unroll
    for (int mt = 0; mt < 2; mt++)
#pragma unroll
        for (int nt = 0; nt < 8; nt++)
#pragma unroll
            for (int qq = 0; qq < 4; qq++) C[mt][nt][qq] = 0.f;

    const int lrow = tid >> 1;
    const int lcol = (tid & 1) * 32;
    const bool arow_ok = (row0 + lrow < NROWS);

    const u32 as_b = (u32)__cvta_generic_to_shared(As);
    const u32 bs_b = (u32)__cvta_generic_to_shared(Bs);
    u32 a_ad[2], b_ad[4];
#pragma unroll
    for (int mt = 0; mt < 2; mt++)
        a_ad[mt] = as_b + ((wm0 + mt * 16 + (q & 1) * 8 + rr) * ASTR + (q >> 1) * 8) * 2;
#pragma unroll
    for (int np = 0; np < 4; np++)
        b_ad[np] = bs_b + ((wn0 + (np * 2 + (q >> 1)) * 8 + rr) * ASTR + (q & 1) * 8) * 2;

    for (int seg = 0; seg < nsegs; seg++) {
        const int we = user ? seg : 2;
        const h16* Asrc = user ? (seg ? g_a_rb : g_a_f) : g_a_r;
        const h16* Wsrc = g_w16 + we * D * D;
#pragma unroll
        for (int st = 0; st < 2; st++) {
            const int kc = st * 64;
            uint4 av[4], wv[4];
            const h16* as_ = Asrc + (size_t)(row0 + lrow) * D + kc + lcol;
            const h16* ws_ = Wsrc + (size_t)lrow * D + kc + lcol;
#pragma unroll
            for (int qq = 0; qq < 4; qq++) {
                av[qq] = arow_ok ? *reinterpret_cast<const uint4*>(as_ + qq * 8)
                                 : make_uint4(0u, 0u, 0u, 0u);
                wv[qq] = *reinterpret_cast<const uint4*>(ws_ + qq * 8);
            }
            __syncthreads();
#pragma unroll
            for (int qq = 0; qq < 4; qq++) {
                *reinterpret_cast<uint4*>(&As[lrow * ASTR + lcol + qq * 8]) = av[qq];
                *reinterpret_cast<uint4*>(&Bs[lrow * ASTR + lcol + qq * 8]) = wv[qq];
            }
            __syncthreads();

#pragma unroll
            for (int ks = 0; ks < 4; ks++) {
                u32 af[2][4];
                ldsm_x4(af[0][0], af[0][1], af[0][2], af[0][3], a_ad[0] + ks * 32);
                ldsm_x4(af[1][0], af[1][1], af[1][2], af[1][3], a_ad[1] + ks * 32);
                u32 bf_[4][4];
#pragma unroll
                for (int np = 0; np < 4; np++)
                    ldsm_x4(bf_[np][0], bf_[np][1], bf_[np][2], bf_[np][3],
                            b_ad[np] + ks * 32);
#pragma unroll
                for (int nt = 0; nt < 8; nt++) {
                    u32 b0 = bf_[nt >> 1][(nt & 1) * 2];
                    u32 b1 = bf_[nt >> 1][(nt & 1) * 2 + 1];
                    mma_f16(C[0][nt], af[0], b0, b1);
                    mma_f16(C[1][nt], af[1], b0, b1);
                }
            }
        }
    }

    const float* bias0 = user ? b_f : b_r;
    const int* cnt0 = user ? g_hist_f : g_hist_r;
    float* out = user ? out_user : out_item;
#pragma unroll
    for (int mt = 0; mt < 2; mt++) {
        int r0 = row0 + wm0 + mt * 16 + g;
        int r1 = r0 + 8;
        bool ok0 = (r0 < NROWS), ok1 = (r1 < NROWS);
        float m00 = (ok0 && cnt0[ok0 ? r0 : 0] > 0) ? 1.f : 0.f;
        float m01 = (ok1 && cnt0[ok1 ? r1 : 0] > 0) ? 1.f : 0.f;
        float m10 = (user && ok0 && g_hist_rb[ok0 ? r0 : 0] > 0) ? 1.f : 0.f;
        float m11 = (user && ok1 && g_hist_rb[ok1 ? r1 : 0] > 0) ? 1.f : 0.f;
#pragma unroll
        for (int nt = 0; nt < 8; nt++) {
            int col = wn0 + nt * 8 + t * 2;
            float bb0 = bias0[col], bb1 = bias0[col + 1];
            float br0 = user ? b_rb[col] : 0.f;
            float br1 = user ? b_rb[col + 1] : 0.f;
            if (ok0) {
                float2 v;
                v.x = C[mt][nt][0] + bb0 * m00 + br0 * m10;
                v.y = C[mt][nt][1] + bb1 * m00 + br1 * m10;
                *reinterpret_cast<float2*>(out + (size_t)r0 * D + col) = v;
            }
            if (ok1) {
                float2 v;
                v.x = C[mt][nt][2] + bb0 * m01 + br0 * m11;
                v.y = C[mt][nt][3] + bb1 * m01 + br1 * m11;
                *reinterpret_cast<float2*>(out + (size_t)r1 * D + col) = v;
            }
        }
    }
}

// ---------------- launch ------------------------------------------------------
extern "C" void kernel_launch(void* const* d_in, const int* in_sizes, int n_in,
                              void* d_out, int out_size)
{
    const float* feat_user = (const float*)d_in[0];
    const float* feat_item = (const float*)d_in[1];
    const float* W_f  = (const float*)d_in[2];
    const float* b_f  = (const float*)d_in[3];
    const float* W_r  = (const float*)d_in[4];
    const float* b_r  = (const float*)d_in[5];
    const float* W_rb = (const float*)d_in[6];
    const float* b_rb = (const float*)d_in[7];
    const int* src_f  = (const int*)d_in[8];
    const int* dst_f  = (const int*)d_in[9];
    const int* src_r  = (const int*)d_in[10];
    const int* dst_r  = (const int*)d_in[11];
    const int* src_rb = (const int*)d_in[12];
    const int* dst_rb = (const int*)d_in[13];
    const int E_f  = in_sizes[8];
    const int E_rb = in_sizes[12];
    const int E_r  = in_sizes[10];

    float* out_user = (float*)d_out;
    float* out_item = (float*)d_out + (size_t)NU * D;

    int Emax = E_f > E_rb ? E_f : E_rb;
    if (E_r > Emax) Emax = E_r;

    zero_hist_kernel<<<(NU + 255) / 256, 256>>>();

    {
        // 3.2M threads: each converts 4 elems of both feat tensors
        size_t n4 = (size_t)NU * D / 4;
        fconv_kernel<<<(unsigned)((n4 + 255) / 256), 256>>>(
            (const float4*)feat_user, (const float4*)feat_item);
    }

    {
        dim3 g((Emax + 255) / 256, 3);
        hist3_kernel<<<g, 256>>>(dst_f, dst_rb, dst_r, E_f, E_rb, E_r);
    }

    wprep_kernel<<<3, 256>>>(W_f, W_rb, W_r);

    {
        dim3 g(SCAN_NB, 3);
        scan_p1<<<g, 256>>>();
        scan_p2<<<1, 3>>>();
        scan_p3<<<g, 256>>>();
    }

    {
        dim3 g((Emax + 255) / 256, 3);
        permute3_kernel<<<g, 256>>>(src_f, dst_f, src_rb, dst_rb, src_r, dst_r,
                                    E_f, E_rb, E_r);
    }

    {
        dim3 g((NROWS * 32 + 255) / 256, 3);
        gather3_kernel<<<g, 256>>>();
    }

    {
        dim3 g((NROWS + 127) / 128, 2);
        gemm_mma<<<g, 256>>>(out_user, out_item, b_f, b_rb, b_r);
    }
}

// round 16
// speedup vs baseline: 1.0824x; 1.0824x over previous
#include <cuda_runtime.h>
#include <cuda_fp16.h>
#include <cstdint>

#define NU 100000
#define NI 100000
#define D  128
#define EMAX 810000
#define NROWS 100000
#define SCAN_NB ((NROWS + 1023) / 1024)

typedef __half h16;
typedef unsigned int u32;

// ---------------- scratch ----------------------------------------------------
__device__ h16 g_a_f [(size_t)NU * D];
__device__ h16 g_a_rb[(size_t)NU * D];
__device__ h16 g_a_r [(size_t)NI * D];
__device__ h16 g_w16[3 * D * D];
__device__ int g_hist_f [NU];
__device__ int g_hist_rb[NU];
__device__ int g_hist_r [NI];
__device__ int g_ptr_f [NU + 1];
__device__ int g_ptr_rb[NU + 1];
__device__ int g_ptr_r [NI + 1];
__device__ int g_cur_f [NU];
__device__ int g_cur_rb[NU];
__device__ int g_cur_r [NI];
__device__ int g_srcl_f [EMAX];
__device__ int g_srcl_rb[EMAX];
__device__ int g_srcl_r [EMAX];
__device__ int g_bsum[3 * SCAN_NB];
__device__ int g_boff[3 * SCAN_NB];

static __device__ __forceinline__ const int* hist_of(int et) {
    return (et == 0) ? g_hist_f : (et == 1) ? g_hist_rb : g_hist_r;
}
static __device__ __forceinline__ int* ptr_of(int et) {
    return (et == 0) ? g_ptr_f : (et == 1) ? g_ptr_rb : g_ptr_r;
}
static __device__ __forceinline__ int* cur_of(int et) {
    return (et == 0) ? g_cur_f : (et == 1) ? g_cur_rb : g_cur_r;
}

// ---------------- zero histograms --------------------------------------------
__global__ void zero_hist_kernel() {
    int i = blockIdx.x * blockDim.x + threadIdx.x;
    if (i < NU) { g_hist_f[i] = 0; g_hist_rb[i] = 0; g_hist_r[i] = 0; }
}

// ---------------- fused histogram ---------------------------------------------
__global__ __launch_bounds__(256) void hist3_kernel(
    const int* __restrict__ d0, const int* __restrict__ d1,
    const int* __restrict__ d2, int E0, int E1, int E2)
{
    int et = blockIdx.y;
    const int* dst = (et == 0) ? d0 : (et == 1) ? d1 : d2;
    int* hist = (et == 0) ? g_hist_f : (et == 1) ? g_hist_rb : g_hist_r;
    int E = (et == 0) ? E0 : (et == 1) ? E1 : E2;
    int i = blockIdx.x * blockDim.x + threadIdx.x;
    if (i < E) atomicAdd(&hist[dst[i]], 1);
}

// ---------------- 3-phase full-chip exclusive scan ----------------------------
__global__ __launch_bounds__(256) void scan_p1()
{
    int et = blockIdx.y;
    const int* hist = hist_of(et);
    int i0 = blockIdx.x * 1024 + threadIdx.x * 4;
    int s = 0;
#pragma unroll
    for (int j = 0; j < 4; j++)
        if (i0 + j < NROWS) s += hist[i0 + j];
    int lane = threadIdx.x & 31, wid = threadIdx.x >> 5;
#pragma unroll
    for (int off = 16; off > 0; off >>= 1)
        s += __shfl_down_sync(0xffffffffu, s, off);
    __shared__ int ws[8];
    if (lane == 0) ws[wid] = s;
    __syncthreads();
    if (threadIdx.x == 0) {
        int tot = 0;
#pragma unroll
        for (int w = 0; w < 8; w++) tot += ws[w];
        g_bsum[et * SCAN_NB + blockIdx.x] = tot;
    }
}

__global__ void scan_p2()
{
    int et = threadIdx.x;
    if (et >= 3) return;
    int run = 0;
    for (int b = 0; b < SCAN_NB; b++) {
        g_boff[et * SCAN_NB + b] = run;
        run += g_bsum[et * SCAN_NB + b];
    }
    ptr_of(et)[NROWS] = run;
}

__global__ __launch_bounds__(256) void scan_p3()
{
    int et = blockIdx.y;
    const int* hist = hist_of(et);
    int* ptr = ptr_of(et);
    int* cur = cur_of(et);
    int i0 = blockIdx.x * 1024 + threadIdx.x * 4;

    int h[4];
    int thsum = 0;
#pragma unroll
    for (int j = 0; j < 4; j++) {
        h[j] = (i0 + j < NROWS) ? hist[i0 + j] : 0;
        thsum += h[j];
    }
    int lane = threadIdx.x & 31, wid = threadIdx.x >> 5;
    int incl = thsum;
#pragma unroll
    for (int off = 1; off < 32; off <<= 1) {
        int t = __shfl_up_sync(0xffffffffu, incl, off);
        if (lane >= off) incl += t;
    }
    __shared__ int ws[8];
    if (lane == 31) ws[wid] = incl;
    __syncthreads();
    int wofs = 0;
#pragma unroll
    for (int w = 0; w < 8; w++)
        if (w < wid) wofs += ws[w];
    int excl = incl - thsum + wofs + g_boff[et * SCAN_NB + blockIdx.x];
#pragma unroll
    for (int j = 0; j < 4; j++) {
        if (i0 + j < NROWS) {
            ptr[i0 + j] = excl;
            cur[i0 + j] = excl;
        }
        excl += h[j];
    }
}

// ---------------- fused permute -----------------------------------------------
__global__ __launch_bounds__(256) void permute3_kernel(
    const int* __restrict__ s0, const int* __restrict__ d0,
    const int* __restrict__ s1, const int* __restrict__ d1,
    const int* __restrict__ s2, const int* __restrict__ d2,
    int E0, int E1, int E2)
{
    int et = blockIdx.y;
    const int* src = (et == 0) ? s0 : (et == 1) ? s1 : s2;
    const int* dst = (et == 0) ? d0 : (et == 1) ? d1 : d2;
    int* cur = cur_of(et);
    int* srclist = (et == 0) ? g_srcl_f : (et == 1) ? g_srcl_rb : g_srcl_r;
    int E = (et == 0) ? E0 : (et == 1) ? E1 : E2;
    int i = blockIdx.x * blockDim.x + threadIdx.x;
    if (i < E) {
        int d = dst[i];
        int p = atomicAdd(&cur[d], 1);
        srclist[p] = src[i];
    }
}

// ---------------- W fp16 prep (wide grid, vectorized) -------------------------
__global__ __launch_bounds__(256) void wprep_kernel(
    const float* __restrict__ Wf, const float* __restrict__ Wrb,
    const float* __restrict__ Wr)
{
    int et = blockIdx.y;
    const float* W = (et == 0) ? Wf : (et == 1) ? Wrb : Wr;
    h16* w = g_w16 + et * D * D;
    int i = (blockIdx.x * 256 + threadIdx.x) * 4;   // 16 blocks x 256 thr x 4
    if (i >= D * D) return;
    float4 x = *reinterpret_cast<const float4*>(W + i);
    u32 p0 = (u32)__half_as_ushort(__float2half_rn(x.x))
           | ((u32)__half_as_ushort(__float2half_rn(x.y)) << 16);
    u32 p1 = (u32)__half_as_ushort(__float2half_rn(x.z))
           | ((u32)__half_as_ushort(__float2half_rn(x.w)) << 16);
    *reinterpret_cast<uint2*>(w + i) = make_uint2(p0, p1);
}

// ---------------- fused gather (R5/R14 form; fp32 feat, fp16 mean out) --------
__global__ __launch_bounds__(256) void gather3_kernel(
    const float4* __restrict__ feat_u, const float4* __restrict__ feat_i)
{
    int et = blockIdx.y;
    const float4* feat = (et == 1) ? feat_i : feat_u;
    const int* ptr = (et == 0) ? g_ptr_f : (et == 1) ? g_ptr_rb : g_ptr_r;
    const int* srclist = (et == 0) ? g_srcl_f : (et == 1) ? g_srcl_rb : g_srcl_r;
    h16* a = (et == 0) ? g_a_f : (et == 1) ? g_a_rb : g_a_r;

    int node = (blockIdx.x * 256 + threadIdx.x) >> 5;
    int lane = threadIdx.x & 31;
    if (node >= NROWS) return;
    int beg = __ldg(&ptr[node]);
    int end = __ldg(&ptr[node + 1]);
    int deg = end - beg;

    float4 s = make_float4(0.f, 0.f, 0.f, 0.f);
    int e = beg;
    for (; e + 8 <= end; e += 8) {
        int si[8];
#pragma unroll
        for (int j = 0; j < 8; j++) si[j] = __ldg(&srclist[e + j]);
        float4 v[8];
#pragma unroll
        for (int j = 0; j < 8; j++) v[j] = feat[(size_t)si[j] * 32 + lane];
#pragma unroll
        for (int j = 0; j < 8; j++) {
            s.x += v[j].x; s.y += v[j].y; s.z += v[j].z; s.w += v[j].w;
        }
    }
    for (; e + 4 <= end; e += 4) {
        int si[4];
#pragma unroll
        for (int j = 0; j < 4; j++) si[j] = __ldg(&srclist[e + j]);
        float4 v[4];
#pragma unroll
        for (int j = 0; j < 4; j++) v[j] = feat[(size_t)si[j] * 32 + lane];
#pragma unroll
        for (int j = 0; j < 4; j++) {
            s.x += v[j].x; s.y += v[j].y; s.z += v[j].z; s.w += v[j].w;
        }
    }
    for (; e < end; e++) {
        float4 v = feat[(size_t)__ldg(&srclist[e]) * 32 + lane];
        s.x += v.x; s.y += v.y; s.z += v.z; s.w += v.w;
    }
    float inv = __fdividef(1.0f, (float)(deg > 0 ? deg : 1));

    u32 p0 = (u32)__half_as_ushort(__float2half_rn(s.x * inv))
           | ((u32)__half_as_ushort(__float2half_rn(s.y * inv)) << 16);
    u32 p1 = (u32)__half_as_ushort(__float2half_rn(s.z * inv))
           | ((u32)__half_as_ushort(__float2half_rn(s.w * inv)) << 16);
    *reinterpret_cast<uint2*>(a + (size_t)node * D + lane * 4) = make_uint2(p0, p1);
}

// ---------------- fp16 mma.sync GEMM (single product) -------------------------
#define ASTR 72

static __device__ __forceinline__ void mma_f16(float* c, const u32* a, u32 b0, u32 b1) {
    asm volatile(
        "mma.sync.aligned.m16n8k16.row.col.f32.f16.f16.f32 "
        "{%0,%1,%2,%3}, {%4,%5,%6,%7}, {%8,%9}, {%0,%1,%2,%3};"
        : "+f"(c[0]), "+f"(c[1]), "+f"(c[2]), "+f"(c[3])
        : "r"(a[0]), "r"(a[1]), "r"(a[2]), "r"(a[3]), "r"(b0), "r"(b1));
}
static __device__ __forceinline__ void ldsm_x4(u32& d0, u32& d1, u32& d2, u32& d3, u32 addr) {
    asm volatile("ldmatrix.sync.aligned.m8n8.x4.shared.b16 {%0,%1,%2,%3}, [%4];"
                 : "=r"(d0), "=r"(d1), "=r"(d2), "=r"(d3) : "r"(addr));
}

__global__ __launch_bounds__(256, 2) void gemm_mma(
    float* __restrict__ out_user, float* __restrict__ out_item,
    const float* __restrict__ b_f, const float* __restrict__ b_rb,
    const float* __restrict__ b_r)
{
    __shared__ __align__(16) h16 As[128 * ASTR];
    __shared__ __align__(16) h16 Bs[128 * ASTR];

    const int tid = threadIdx.x;
    const int wid = tid >> 5, lane = tid & 31;
    const int g = lane >> 2, t = lane & 3;
    const int q = lane >> 3, rr = lane & 7;
    const int row0 = blockIdx.x * 128;
    const bool user = (blockIdx.y == 0);
    const int nsegs = user ? 2 : 1;

    const int wm0 = (wid >> 1) * 32;
    const int wn0 = (wid & 1) * 64;

    float C[2][8][4];
#pragma unroll
    for (int mt = 0; mt < 2; mt++)
#pragma unroll
        for (int nt = 0; nt < 8; nt++)
#pragma unroll
            for (int qq = 0; qq < 4; qq++) C[mt][nt][qq] = 0.f;

    const int lrow = tid >> 1;
    const int lcol = (tid & 1) * 32;
    const bool arow_ok = (row0 + lrow < NROWS);

    const u32 as_b = (u32)__cvta_generic_to_shared(As);
    const u32 bs_b = (u32)__cvta_generic_to_shared(Bs);
    u32 a_ad[2], b_ad[4];
#pragma unroll
    for (int mt = 0; mt < 2; mt++)
        a_ad[mt] = as_b + ((wm0 + mt * 16 + (q & 1) * 8 + rr) * ASTR + (q >> 1) * 8) * 2;
#pragma unroll
    for (int np = 0; np < 4; np++)
        b_ad[np] = bs_b + ((wn0 + (np * 2 + (q >> 1)) * 8 + rr) * ASTR + (q & 1) * 8) * 2;

    for (int seg = 0; seg < nsegs; seg++) {
        const int we = user ? seg : 2;
        const h16* Asrc = user ? (seg ? g_a_rb : g_a_f) : g_a_r;
        const h16* Wsrc = g_w16 + we * D * D;
#pragma unroll
        for (int st = 0; st < 2; st++) {
            const int kc = st * 64;
            uint4 av[4], wv[4];
            const h16* as_ = Asrc + (size_t)(row0 + lrow) * D + kc + lcol;
            const h16* ws_ = Wsrc + (size_t)lrow * D + kc + lcol;
#pragma unroll
            for (int qq = 0; qq < 4; qq++) {
                av[qq] = arow_ok ? *reinterpret_cast<const uint4*>(as_ + qq * 8)
                                 : make_uint4(0u, 0u, 0u, 0u);
                wv[qq] = *reinterpret_cast<const uint4*>(ws_ + qq * 8);
            }
            __syncthreads();
#pragma unroll
            for (int qq = 0; qq < 4; qq++) {
                *reinterpret_cast<uint4*>(&As[lrow * ASTR + lcol + qq * 8]) = av[qq];
                *reinterpret_cast<uint4*>(&Bs[lrow * ASTR + lcol + qq * 8]) = wv[qq];
            }
            __syncthreads();

#pragma unroll
            for (int ks = 0; ks < 4; ks++) {
                u32 af[2][4];
                ldsm_x4(af[0][0], af[0][1], af[0][2], af[0][3], a_ad[0] + ks * 32);
                ldsm_x4(af[1][0], af[1][1], af[1][2], af[1][3], a_ad[1] + ks * 32);
                u32 bf_[4][4];
#pragma unroll
                for (int np = 0; np < 4; np++)
                    ldsm_x4(bf_[np][0], bf_[np][1], bf_[np][2], bf_[np][3],
                            b_ad[np] + ks * 32);
#pragma unroll
                for (int nt = 0; nt < 8; nt++) {
                    u32 b0 = bf_[nt >> 1][(nt & 1) * 2];
                    u32 b1 = bf_[nt >> 1][(nt & 1) * 2 + 1];
                    mma_f16(C[0][nt], af[0], b0, b1);
                    mma_f16(C[1][nt], af[1], b0, b1);
                }
            }
        }
    }

    const float* bias0 = user ? b_f : b_r;
    const int* cnt0 = user ? g_hist_f : g_hist_r;
    float* out = user ? out_user : out_item;
#pragma unroll
    for (int mt = 0; mt < 2; mt++) {
        int r0 = row0 + wm0 + mt * 16 + g;
        int r1 = r0 + 8;
        bool ok0 = (r0 < NROWS), ok1 = (r1 < NROWS);
        float m00 = (ok0 && cnt0[ok0 ? r0 : 0] > 0) ? 1.f : 0.f;
        float m01 = (ok1 && cnt0[ok1 ? r1 : 0] > 0) ? 1.f : 0.f;
        float m10 = (user && ok0 && g_hist_rb[ok0 ? r0 : 0] > 0) ? 1.f : 0.f;
        float m11 = (user && ok1 && g_hist_rb[ok1 ? r1 : 0] > 0) ? 1.f : 0.f;
#pragma unroll
        for (int nt = 0; nt < 8; nt++) {
            int col = wn0 + nt * 8 + t * 2;
            float bb0 = bias0[col], bb1 = bias0[col + 1];
            float br0 = user ? b_rb[col] : 0.f;
            float br1 = user ? b_rb[col + 1] : 0.f;
            if (ok0) {
                float2 v;
                v.x = C[mt][nt][0] + bb0 * m00 + br0 * m10;
                v.y = C[mt][nt][1] + bb1 * m00 + br1 * m10;
                *reinterpret_cast<float2*>(out + (size_t)r0 * D + col) = v;
            }
            if (ok1) {
                float2 v;
                v.x = C[mt][nt][2] + bb0 * m01 + br0 * m11;
                v.y = C[mt][nt][3] + bb1 * m01 + br1 * m11;
                *reinterpret_cast<float2*>(out + (size_t)r1 * D + col) = v;
            }
        }
    }
}

// ---------------- launch ------------------------------------------------------
extern "C" void kernel_launch(void* const* d_in, const int* in_sizes, int n_in,
                              void* d_out, int out_size)
{
    const float* feat_user = (const float*)d_in[0];
    const float* feat_item = (const float*)d_in[1];
    const float* W_f  = (const float*)d_in[2];
    const float* b_f  = (const float*)d_in[3];
    const float* W_r  = (const float*)d_in[4];
    const float* b_r  = (const float*)d_in[5];
    const float* W_rb = (const float*)d_in[6];
    const float* b_rb = (const float*)d_in[7];
    const int* src_f  = (const int*)d_in[8];
    const int* dst_f  = (const int*)d_in[9];
    const int* src_r  = (const int*)d_in[10];
    const int* dst_r  = (const int*)d_in[11];
    const int* src_rb = (const int*)d_in[12];
    const int* dst_rb = (const int*)d_in[13];
    const int E_f  = in_sizes[8];
    const int E_rb = in_sizes[12];
    const int E_r  = in_sizes[10];

    float* out_user = (float*)d_out;
    float* out_item = (float*)d_out + (size_t)NU * D;

    int Emax = E_f > E_rb ? E_f : E_rb;
    if (E_r > Emax) Emax = E_r;

    zero_hist_kernel<<<(NU + 255) / 256, 256>>>();

    {
        dim3 g((Emax + 255) / 256, 3);
        hist3_kernel<<<g, 256>>>(dst_f, dst_rb, dst_r, E_f, E_rb, E_r);
    }

    {
        // 16 blocks x 256 threads x 4 elems = 16384 = D*D per etype
        dim3 g((D * D / 4 + 255) / 256, 3);
        wprep_kernel<<<g, 256>>>(W_f, W_rb, W_r);
    }

    {
        dim3 g(SCAN_NB, 3);
        scan_p1<<<g, 256>>>();
        scan_p2<<<1, 3>>>();
        scan_p3<<<g, 256>>>();
    }

    {
        dim3 g((Emax + 255) / 256, 3);
        permute3_kernel<<<g, 256>>>(src_f, dst_f, src_rb, dst_rb, src_r, dst_r,
                                    E_f, E_rb, E_r);
    }

    {
        dim3 g((NROWS * 32 + 255) / 256, 3);
        gather3_kernel<<<g, 256>>>((const float4*)feat_user,
                                   (const float4*)feat_item);
    }

    {
        dim3 g((NROWS + 127) / 128, 2);
        gemm_mma<<<g, 256>>>(out_user, out_item, b_f, b_rb, b_r);
    }
}